// round 13
// baseline (speedup 1.0000x reference)
#include <cuda_runtime.h>

#define B_      64
#define S_      200
#define DK_     32
#define NQ1     4097
#define NCHT    129           // 32-row chunks, padded to 4128 rows
#define CROWS   32
#define NBB     9             // blocks per batch
#define NBLK    (B_ * NBB)    // 576 <= 148*4
#define TSTEPS  199
#define CHF     1024          // floats per chunk (32k x 32r)

// g_h layout: [b][chunk][k=32][r=32] with r swizzled: rsw = r ^ (8*(k&3)).
static __device__ float g_h[(size_t)B_ * NCHT * CHF];
static __device__ float g_ht[S_ * B_ * DK_];
static __device__ float g_learn[S_ * B_ * DK_];
static __device__ float g_it[S_ * B_ * DK_];
static __device__ int   g_flag[B_];

typedef unsigned long long ull;

__device__ __forceinline__ unsigned smem_u32(const void* p) {
    unsigned a;
    asm("{ .reg .u64 t; cvta.to.shared.u64 t, %1; cvt.u32.u64 %0, t; }" : "=r"(a) : "l"(p));
    return a;
}
__device__ __forceinline__ void bulk_g2s(unsigned sdst, const void* gsrc, unsigned bytes,
                                         unsigned mbar) {
    asm volatile(
        "cp.async.bulk.shared::cta.global.mbarrier::complete_tx::bytes [%0], [%1], %2, [%3];"
        :: "r"(sdst), "l"(gsrc), "r"(bytes), "r"(mbar) : "memory");
}
__device__ __forceinline__ void mbar_wait(unsigned mbar, unsigned phase) {
    asm volatile(
        "{\n\t.reg .pred P;\n\t"
        "W_%=:\n\t"
        "mbarrier.try_wait.parity.shared.b64 P, [%0], %1, 0x989680;\n\t"
        "@P bra D_%=;\n\t"
        "bra.uni W_%=;\n\t"
        "D_%=:\n\t}"
        :: "r"(mbar), "r"(phase) : "memory");
}
__device__ __forceinline__ float tf32hi(float v) {
    return __uint_as_float(__float_as_uint(v) & 0xFFFFE000u);
}
__device__ __forceinline__ void mma8(float* c, const float* a, const float* b) {
    asm("mma.sync.aligned.m16n8k8.row.col.f32.tf32.tf32.f32 "
        "{%0,%1,%2,%3}, {%4,%5,%6,%7}, {%8,%9}, {%0,%1,%2,%3};"
        : "+f"(c[0]), "+f"(c[1]), "+f"(c[2]), "+f"(c[3])
        : "r"(__float_as_uint(a[0])), "r"(__float_as_uint(a[1])),
          "r"(__float_as_uint(a[2])), "r"(__float_as_uint(a[3])),
          "r"(__float_as_uint(b[0])), "r"(__float_as_uint(b[1])));
}

// ---------------------------------------------------------------------------
// K1: init g_h (swizzled layout, padding zeroed), zero h_tilde, flags, pred0
// ---------------------------------------------------------------------------
__global__ void k_init(const float* __restrict__ h0, float* __restrict__ pred) {
    const int PERB = NCHT * CHF;  // 132096
    int stride = gridDim.x * blockDim.x;
    long total = (long)B_ * PERB;
    for (long i = blockIdx.x * blockDim.x + threadIdx.x; i < total; i += stride) {
        int b = (int)(i / PERB);
        int rem = (int)(i - (long)b * PERB);
        int c = rem >> 10;
        int kk = (rem & 1023) >> 5;
        int rsw = rem & 31;
        int r = rsw ^ (8 * (kk & 3));
        int grow = c * CROWS + r;
        g_h[i] = (grow < NQ1) ? h0[grow * DK_ + kk] : 0.0f;
    }
    int gid = blockIdx.x * blockDim.x + threadIdx.x;
    for (int i = gid; i < S_ * B_ * DK_; i += stride) g_ht[i] = 0.0f;
    if (gid < B_) { pred[gid * S_] = 0.0f; g_flag[gid] = 0; }
}

// ---------------------------------------------------------------------------
__global__ void k_embed(const int* __restrict__ e_data, const int* __restrict__ at_data,
                        const int* __restrict__ it_data, const float* __restrict__ a_data,
                        const float* __restrict__ E_e, const float* __restrict__ E_at,
                        const float* __restrict__ E_it,
                        const float* __restrict__ W1, const float* __restrict__ b1) {
    int idx = blockIdx.x * blockDim.x + threadIdx.x;
    if (idx >= S_ * B_ * DK_) return;
    int t = idx / (B_ * DK_);
    int rem = idx - t * (B_ * DK_);
    int b = rem >> 5;
    int k = rem & 31;
    int e  = e_data[b * S_ + t];
    int at = at_data[b * S_ + t];
    int it = it_data[b * S_ + t];
    float a = a_data[b * S_ + t];
    const float* ee  = E_e  + e  * DK_;
    const float* eat = E_at + at * DK_;
    const float* w1k = W1 + k * (3 * DK_);
    float s = b1[k];
    float ws = 0.0f;
#pragma unroll
    for (int j = 0; j < DK_; j++) {
        s = fmaf(ee[j],  w1k[j],       s);
        s = fmaf(eat[j], w1k[DK_ + j], s);
        ws += w1k[2 * DK_ + j];
    }
    s = fmaf(a, ws, s);
    g_learn[(t * B_ + b) * DK_ + k] = s;
    g_it[(t * B_ + b) * DK_ + k]    = E_it[it * DK_ + k];
}

// ---------------------------------------------------------------------------
__global__ void k_ht0(const int* __restrict__ e_data, const float* __restrict__ q,
                      const float* __restrict__ h0) {
    int b = blockIdx.x;
    int w = threadIdx.x >> 5;
    int lane = threadIdx.x & 31;
    const float* qr = q + (long)e_data[b * S_] * NQ1;
    float acc = 0.0f;
    for (int n = w; n < NQ1; n += 8) {
        float qv = qr[n];
        if (qv != 0.0f) acc = fmaf(qv, h0[n * DK_ + lane], acc);
    }
    atomicAdd(&g_ht[b * DK_ + lane], acc);
}

// ---------------------------------------------------------------------------
// k_seq: persistent, 576 blocks (64 batches x 9), 128 threads, 4 CTAs/SM.
//   Phase A: warp w computes Z for its 8-row n-tile via tf32 mma (W frags in
//   regs, hi/lo 3-term). Phase B: lane=row epilogue over 8 dims per warp.
// ---------------------------------------------------------------------------
__global__ void __launch_bounds__(128, 4)
k_seq(const int* __restrict__ e_data, const float* __restrict__ q,
      const float* __restrict__ E_e,
      const float* __restrict__ W2, const float* __restrict__ b2,
      const float* __restrict__ W3, const float* __restrict__ b3,
      const float* __restrict__ W4, const float* __restrict__ b4,
      const float* __restrict__ W5, const float* __restrict__ b5,
      float* __restrict__ pred) {
    __shared__ __align__(16) float sh_h[2][CHF];        // 2 x 4KB
    __shared__ __align__(16) float sh_z[2][CROWS * 33]; // 2 x 4224B
    __shared__ __align__(16) float sh_qe[2][48];
    __shared__ __align__(16) float sh_qn[2][48];
    __shared__ __align__(8)  ull   sh_mbar[2];
    __shared__ int   sh_cnt[2];
    __shared__ float sh_x[4 * DK_];
    __shared__ float sh_LG[DK_];
    __shared__ float sh_cv[DK_];
    __shared__ float sh_gl[DK_];
    __shared__ float sh_cB[DK_];

    const int gbl = blockIdx.x;
    const int tid = threadIdx.x;
    const int w = tid >> 5;
    const int lane = tid & 31;
    const int g2 = lane >> 2;      // groupID
    const int tg = lane & 3;       // threadID_in_group

    const int b = gbl / NBB;
    const int ib = gbl - b * NBB;
    const int clo = (ib * NCHT) / NBB;
    const int chi = ((ib + 1) * NCHT) / NBB;
    const int nch = chi - clo;
    const int total_u = TSTEPS * nch;

    const unsigned mb_full = smem_u32(&sh_mbar[0]);

    if (tid == 0) {
#pragma unroll
        for (int s = 0; s < 2; s++) {
            asm volatile("mbarrier.init.shared.b64 [%0], 1;" :: "r"(mb_full + s * 8));
            sh_cnt[s] = 0;
        }
        asm volatile("fence.proxy.async.shared::cta;" ::: "memory");
    }
    __syncthreads();

#define ISSUE_U(U)                                                                      \
    {                                                                                   \
        int tu = (U) / nch;                                                             \
        int cu = (U) - tu * nch;                                                        \
        int gc = clo + cu;                                                              \
        int rs_ = gc * CROWS;                                                           \
        int sl_ = (U) & 1;                                                              \
        unsigned mb = mb_full + sl_ * 8;                                                \
        int etu = e_data[b * S_ + tu];                                                  \
        int enu = e_data[b * S_ + tu + 1];                                              \
        ull pe = (ull)(q + (long)etu * NQ1 + rs_);                                      \
        ull pn = (ull)(q + (long)enu * NQ1 + rs_);                                      \
        unsigned qeb = ((128u + (unsigned)(pe & 15)) + 15) & ~15u;                      \
        unsigned qnb = ((128u + (unsigned)(pn & 15)) + 15) & ~15u;                      \
        asm volatile("mbarrier.arrive.expect_tx.shared.b64 _, [%0], %1;"                \
                     :: "r"(mb), "r"(4096u + qeb + qnb) : "memory");                    \
        bulk_g2s(smem_u32(&sh_h[sl_][0]), g_h + ((size_t)b * NCHT + gc) * CHF,          \
                 4096u, mb);                                                            \
        bulk_g2s(smem_u32(&sh_qe[sl_][0]), (const void*)(pe & ~15ULL), qeb, mb);        \
        bulk_g2s(smem_u32(&sh_qn[sl_][0]), (const void*)(pn & ~15ULL), qnb, mb);        \
    }

    if (tid == 0) { ISSUE_U(0) ISSUE_U(1) }

    // ---- W4h fragments (hi/lo), loaded once: ah/al[mt][kt][4] ----
    float ah[2][4][4], al[2][4][4];
#pragma unroll
    for (int mt = 0; mt < 2; mt++)
#pragma unroll
        for (int kt = 0; kt < 4; kt++) {
            int d0 = g2 + 16 * mt, d1 = d0 + 8;
            int k0 = 8 * kt + tg,  k1 = k0 + 4;
            float v0 = W4[d0 * 96 + k0];
            float v1 = W4[d1 * 96 + k0];
            float v2 = W4[d0 * 96 + k1];
            float v3 = W4[d1 * 96 + k1];
            ah[mt][kt][0] = tf32hi(v0); al[mt][kt][0] = v0 - ah[mt][kt][0];
            ah[mt][kt][1] = tf32hi(v1); al[mt][kt][1] = v1 - ah[mt][kt][1];
            ah[mt][kt][2] = tf32hi(v2); al[mt][kt][2] = v2 - ah[mt][kt][2];
            ah[mt][kt][3] = tf32hi(v3); al[mt][kt][3] = v3 - ah[mt][kt][3];
        }

    const int nofs = w * 8;        // phase A n-tile base
    const int dbase = w * 8;       // phase B dim base
    int u = 0;

    for (int t = 0; t < TSTEPS; t++) {
        if (t > 0) {
            if (tid == 0) {
                int need = NBB * t;
                int v;
                do {
                    asm volatile("ld.global.acquire.gpu.b32 %0, [%1];"
                                 : "=r"(v) : "l"(&g_flag[b]));
                    if (v >= need) break;
                    __nanosleep(64);
                } while (true);
            }
            __syncthreads();
        }

        const int e_t = e_data[b * S_ + t];
        const int e_n = e_data[b * S_ + t + 1];

        // ---- prologue: warps 0 (lg), 1 (gl), 2 (cB); warp 3 y-pred ----
        if (w < 3) {
            if (w == 0) {
                sh_x[lane]           = (t == 0) ? 0.0f : g_learn[((t - 1) * B_ + b) * DK_ + lane];
                sh_x[DK_ + lane]     = g_it[(t * B_ + b) * DK_ + lane];
                sh_x[2 * DK_ + lane] = g_learn[(t * B_ + b) * DK_ + lane];
                sh_x[3 * DK_ + lane] = g_ht[(t * B_ + b) * DK_ + lane];
            }
            asm volatile("bar.sync 7, 96;" ::: "memory");
            float lg = 0.0f;
            if (w == 0) {
                const float4* wk = (const float4*)(W2 + lane * 128);
                const float4* xv4 = (const float4*)sh_x;
                float a0 = b2[lane], a1 = 0.f, a2 = 0.f, a3 = 0.f;
#pragma unroll
                for (int j = 0; j < 32; j++) {
                    float4 xv = xv4[j]; float4 wa = wk[j];
                    a0 = fmaf(xv.x, wa.x, a0); a1 = fmaf(xv.y, wa.y, a1);
                    a2 = fmaf(xv.z, wa.z, a2); a3 = fmaf(xv.w, wa.w, a3);
                }
                lg = (a0 + a1) + (a2 + a3);
            } else if (w == 1) {
                const float4* wk = (const float4*)(W3 + lane * 128);
                const float4* xv4 = (const float4*)sh_x;
                float a0 = b3[lane], a1 = 0.f, a2 = 0.f, a3 = 0.f;
#pragma unroll
                for (int j = 0; j < 32; j++) {
                    float4 xv = xv4[j]; float4 wa = wk[j];
                    a0 = fmaf(xv.x, wa.x, a0); a1 = fmaf(xv.y, wa.y, a1);
                    a2 = fmaf(xv.z, wa.z, a2); a3 = fmaf(xv.w, wa.w, a3);
                }
                float gl = (a0 + a1) + (a2 + a3);
                sh_gl[lane] = 1.0f / (1.0f + expf(-gl));
            } else {
                const float* wk = W4 + lane * (3 * DK_) + 2 * DK_;
                float a0 = b4[lane], a1 = 0.f;
#pragma unroll
                for (int j = 0; j < DK_; j += 2) {
                    a0 = fmaf(sh_x[DK_ + j],     wk[j],     a0);
                    a1 = fmaf(sh_x[DK_ + j + 1], wk[j + 1], a1);
                }
                sh_cB[lane] = a0 + a1;
            }
            asm volatile("bar.sync 7, 96;" ::: "memory");
            if (w == 0) {
                lg = tanhf(lg);
                sh_LG[lane] = sh_gl[lane] * (lg + 1.0f) * 0.5f;
                __syncwarp();
                const float* w4l = W4 + lane * (3 * DK_) + DK_;
                float c0 = sh_cB[lane], c1 = 0.f;
#pragma unroll
                for (int j = 0; j < DK_; j += 2) {
                    c0 = fmaf(sh_LG[j],     w4l[j],     c0);
                    c1 = fmaf(sh_LG[j + 1], w4l[j + 1], c1);
                }
                sh_cv[lane] = c0 + c1;
            }
        } else if (ib == 0 && t > 0) {
            const float* ee = E_e + e_t * DK_;
            const float* ht = g_ht + (t * B_ + b) * DK_;
            const float* w5k = W5 + lane * (2 * DK_);
            float z = b5[lane];
#pragma unroll
            for (int j = 0; j < DK_; j++) {
                z = fmaf(ee[j], w5k[j], z);
                z = fmaf(ht[j], w5k[DK_ + j], z);
            }
            float s = 1.0f / (1.0f + expf(-z));
#pragma unroll
            for (int off = 16; off; off >>= 1)
                s += __shfl_xor_sync(0xffffffffu, s, off);
            if (lane == 0) pred[b * S_ + t] = s * (1.0f / DK_);
        }
        __syncthreads();

        const float cv_reg = sh_cv[lane];
        const float LG_reg = sh_LG[lane];
        float* htn = g_ht + ((t + 1) * B_ + b) * DK_;

        for (int c = 0; c < nch; c++, u++) {
            const int slot = u & 1;
            const unsigned phase = (u >> 1) & 1;
            mbar_wait(mb_full + slot * 8, phase);

            const int gc = clo + c;
            const int rs = gc * CROWS;
            float* tile = sh_h[slot];
            float* zt = sh_z[slot];

            // ---- Phase A: 8-row n-tile per warp via tf32 mma ----
            {
                float bh[4][2], bl[4][2];
                const int xr = (nofs + g2) ^ (8 * tg);
#pragma unroll
                for (int kt = 0; kt < 4; kt++) {
                    int k0 = 8 * kt + tg;
                    float v0 = tile[k0 * 32 + xr];
                    float v1 = tile[(k0 + 4) * 32 + xr];
                    bh[kt][0] = tf32hi(v0); bl[kt][0] = v0 - bh[kt][0];
                    bh[kt][1] = tf32hi(v1); bl[kt][1] = v1 - bh[kt][1];
                }
                float C0[4] = {0.f, 0.f, 0.f, 0.f};
                float C1[4] = {0.f, 0.f, 0.f, 0.f};
#pragma unroll
                for (int kt = 0; kt < 4; kt++) {
                    mma8(C0, ah[0][kt], bh[kt]);
                    mma8(C1, ah[1][kt], bh[kt]);
                }
#pragma unroll
                for (int kt = 0; kt < 4; kt++) {
                    mma8(C0, ah[0][kt], bl[kt]);
                    mma8(C1, ah[1][kt], bl[kt]);
                }
#pragma unroll
                for (int kt = 0; kt < 4; kt++) {
                    mma8(C0, al[0][kt], bh[kt]);
                    mma8(C1, al[1][kt], bh[kt]);
                }
                const int r0 = nofs + 2 * tg;
                zt[r0 * 33 + g2]            = C0[0];
                zt[(r0 + 1) * 33 + g2]      = C0[1];
                zt[r0 * 33 + g2 + 8]        = C0[2];
                zt[(r0 + 1) * 33 + g2 + 8]  = C0[3];
                zt[r0 * 33 + g2 + 16]       = C1[0];
                zt[(r0 + 1) * 33 + g2 + 16] = C1[1];
                zt[r0 * 33 + g2 + 24]       = C1[2];
                zt[(r0 + 1) * 33 + g2 + 24] = C1[3];
            }
            __syncthreads();

            // ---- Phase B: lane=row, 8 dims per warp ----
            {
                const bool valid = (rs + lane) < NQ1;
                const int qoe = (int)(((ull)(q + (long)e_t * NQ1 + rs) >> 2) & 3);
                const int qon = (int)(((ull)(q + (long)e_n * NQ1 + rs) >> 2) & 3);
                const float qe_l = valid ? sh_qe[slot][qoe + lane] : 0.0f;
                const float qn_l = valid ? sh_qn[slot][qon + lane] : 0.0f;
                const unsigned anyq = __ballot_sync(0xffffffffu, qn_l != 0.0f);
                float* gob = g_h + ((size_t)b * NCHT + gc) * CHF;
#pragma unroll
                for (int j = 0; j < 8; j++) {
                    const int d = dbase + j;
                    const int xo = lane ^ (8 * (d & 3));
                    float z = zt[lane * 33 + d];
                    float hk = tile[d * 32 + xo];
                    float cd = __shfl_sync(0xffffffffu, cv_reg, d);
                    float LGd = __shfl_sync(0xffffffffu, LG_reg, d);
                    float gm = __fdividef(1.0f, 1.0f + __expf(-(z + cd)));
                    float hn = fmaf(gm, hk, qe_l * LGd);
                    gob[d * 32 + xo] = hn;
                    if (anyq) {
                        float v = qn_l * hn;
#pragma unroll
                        for (int off = 16; off; off >>= 1)
                            v += __shfl_xor_sync(0xffffffffu, v, off);
                        if (lane == 0) atomicAdd(htn + d, v);
                    }
                }
            }

            if (lane == 0) {
                int old = atomicAdd(&sh_cnt[slot], 1);
                if ((old & 3) == 3) {
                    __threadfence();
                    const int un = u + 2;
                    if (un < total_u) ISSUE_U(un)
                }
            }
        }

        __threadfence();
        __syncthreads();
        if (tid == 0 && t < TSTEPS - 1) atomicAdd(&g_flag[b], 1);
    }
#undef ISSUE_U
}

// ---------------------------------------------------------------------------
__global__ void k_final(const int* __restrict__ e_data, const float* __restrict__ E_e,
                        const float* __restrict__ W5, const float* __restrict__ b5,
                        float* __restrict__ pred) {
    int b = blockIdx.x;
    int k = threadIdx.x;
    int tlast = S_ - 1;
    int en = e_data[b * S_ + tlast];
    const float* ee = E_e + en * DK_;
    const float* ht = g_ht + (tlast * B_ + b) * DK_;
    const float* w5k = W5 + k * (2 * DK_);
    float z = b5[k];
#pragma unroll
    for (int j = 0; j < DK_; j++) {
        z = fmaf(ee[j], w5k[j], z);
        z = fmaf(ht[j], w5k[DK_ + j], z);
    }
    float s = 1.0f / (1.0f + expf(-z));
#pragma unroll
    for (int off = 16; off; off >>= 1)
        s += __shfl_xor_sync(0xffffffffu, s, off);
    if (k == 0) pred[b * S_ + tlast] = s * (1.0f / DK_);
}

// ---------------------------------------------------------------------------
extern "C" void kernel_launch(void* const* d_in, const int* in_sizes, int n_in,
                              void* d_out, int out_size) {
    const int*   e_data  = (const int*)d_in[0];
    const int*   at_data = (const int*)d_in[1];
    const int*   it_data = (const int*)d_in[2];
    const float* a_data  = (const float*)d_in[3];
    const float* q       = (const float*)d_in[4];
    const float* E_e     = (const float*)d_in[5];
    const float* E_at    = (const float*)d_in[6];
    const float* E_it    = (const float*)d_in[7];
    const float* W1      = (const float*)d_in[8];
    const float* b1      = (const float*)d_in[9];
    const float* W2      = (const float*)d_in[10];
    const float* b2      = (const float*)d_in[11];
    const float* W3      = (const float*)d_in[12];
    const float* b3      = (const float*)d_in[13];
    const float* W4      = (const float*)d_in[14];
    const float* b4      = (const float*)d_in[15];
    const float* W5      = (const float*)d_in[16];
    const float* b5      = (const float*)d_in[17];
    const float* h0      = (const float*)d_in[18];
    float* pred = (float*)d_out;

    k_init<<<2048, 256>>>(h0, pred);
    k_embed<<<(S_ * B_ * DK_ + 255) / 256, 256>>>(e_data, at_data, it_data, a_data,
                                                  E_e, E_at, E_it, W1, b1);
    k_ht0<<<B_, 256>>>(e_data, q, h0);

    k_seq<<<NBLK, 128>>>(e_data, q, E_e, W2, b2, W3, b3, W4, b4, W5, b5, pred);

    k_final<<<B_, 32>>>(e_data, E_e, W5, b5, pred);
}

// round 14
// speedup vs baseline: 1.3525x; 1.3525x over previous
#include <cuda_runtime.h>

#define B_      64
#define S_      200
#define DK_     32
#define NQ1     4097
#define NCH64   65            // 64-row chunks per batch (4160 rows padded)
#define NMC     130           // 32-row microchunks per batch
#define NBLK    296           // 148 SMs x 2 CTAs exactly
#define TSTEPS  199

// g_h layout: [b][microchunk][k=32][r=32], r swizzled: rsw = r ^ (8*(k&3)).
static __device__ float g_h[(size_t)B_ * NMC * 1024];
static __device__ float g_ht[S_ * B_ * DK_];
static __device__ float g_learn[S_ * B_ * DK_];
static __device__ float g_it[S_ * B_ * DK_];
static __device__ int   g_flag[B_];

typedef unsigned long long ull;

__device__ __forceinline__ unsigned smem_u32(const void* p) {
    unsigned a;
    asm("{ .reg .u64 t; cvta.to.shared.u64 t, %1; cvt.u32.u64 %0, t; }" : "=r"(a) : "l"(p));
    return a;
}
__device__ __forceinline__ void bulk_g2s(unsigned sdst, const void* gsrc, unsigned bytes,
                                         unsigned mbar) {
    asm volatile(
        "cp.async.bulk.shared::cta.global.mbarrier::complete_tx::bytes [%0], [%1], %2, [%3];"
        :: "r"(sdst), "l"(gsrc), "r"(bytes), "r"(mbar) : "memory");
}
__device__ __forceinline__ void mbar_wait(unsigned mbar, unsigned phase) {
    asm volatile(
        "{\n\t.reg .pred P;\n\t"
        "W_%=:\n\t"
        "mbarrier.try_wait.parity.shared.b64 P, [%0], %1, 0x989680;\n\t"
        "@P bra D_%=;\n\t"
        "bra.uni W_%=;\n\t"
        "D_%=:\n\t}"
        :: "r"(mbar), "r"(phase) : "memory");
}
__device__ __forceinline__ float tf32hi(float v) {
    return __uint_as_float(__float_as_uint(v) & 0xFFFFE000u);
}
__device__ __forceinline__ void mma8(float* c, const float* a, const float* b) {
    asm("mma.sync.aligned.m16n8k8.row.col.f32.tf32.tf32.f32 "
        "{%0,%1,%2,%3}, {%4,%5,%6,%7}, {%8,%9}, {%0,%1,%2,%3};"
        : "+f"(c[0]), "+f"(c[1]), "+f"(c[2]), "+f"(c[3])
        : "r"(__float_as_uint(a[0])), "r"(__float_as_uint(a[1])),
          "r"(__float_as_uint(a[2])), "r"(__float_as_uint(a[3])),
          "r"(__float_as_uint(b[0])), "r"(__float_as_uint(b[1])));
}

// ---------------------------------------------------------------------------
// K1: init g_h (swizzled, padding zeroed), zero h_tilde, flags, pred[:,0]=0
// ---------------------------------------------------------------------------
__global__ void k_init(const float* __restrict__ h0, float* __restrict__ pred) {
    const int PERB = NMC * 1024;
    int stride = gridDim.x * blockDim.x;
    long total = (long)B_ * PERB;
    for (long i = blockIdx.x * blockDim.x + threadIdx.x; i < total; i += stride) {
        int b = (int)(i / PERB);
        int rem = (int)(i - (long)b * PERB);
        int mc = rem >> 10;
        int kk = (rem & 1023) >> 5;
        int rsw = rem & 31;
        int r = rsw ^ (8 * (kk & 3));
        int grow = mc * 32 + r;
        g_h[i] = (grow < NQ1) ? h0[grow * DK_ + kk] : 0.0f;
    }
    int gid = blockIdx.x * blockDim.x + threadIdx.x;
    for (int i = gid; i < S_ * B_ * DK_; i += stride) g_ht[i] = 0.0f;
    if (gid < B_) { pred[gid * S_] = 0.0f; g_flag[gid] = 0; }
}

// ---------------------------------------------------------------------------
__global__ void k_embed(const int* __restrict__ e_data, const int* __restrict__ at_data,
                        const int* __restrict__ it_data, const float* __restrict__ a_data,
                        const float* __restrict__ E_e, const float* __restrict__ E_at,
                        const float* __restrict__ E_it,
                        const float* __restrict__ W1, const float* __restrict__ b1) {
    int idx = blockIdx.x * blockDim.x + threadIdx.x;
    if (idx >= S_ * B_ * DK_) return;
    int t = idx / (B_ * DK_);
    int rem = idx - t * (B_ * DK_);
    int b = rem >> 5;
    int k = rem & 31;
    int e  = e_data[b * S_ + t];
    int at = at_data[b * S_ + t];
    int it = it_data[b * S_ + t];
    float a = a_data[b * S_ + t];
    const float* ee  = E_e  + e  * DK_;
    const float* eat = E_at + at * DK_;
    const float* w1k = W1 + k * (3 * DK_);
    float s = b1[k];
    float ws = 0.0f;
#pragma unroll
    for (int j = 0; j < DK_; j++) {
        s = fmaf(ee[j],  w1k[j],       s);
        s = fmaf(eat[j], w1k[DK_ + j], s);
        ws += w1k[2 * DK_ + j];
    }
    s = fmaf(a, ws, s);
    g_learn[(t * B_ + b) * DK_ + k] = s;
    g_it[(t * B_ + b) * DK_ + k]    = E_it[it * DK_ + k];
}

// ---------------------------------------------------------------------------
__global__ void k_ht0(const int* __restrict__ e_data, const float* __restrict__ q,
                      const float* __restrict__ h0) {
    int b = blockIdx.x;
    int w = threadIdx.x >> 5;
    int lane = threadIdx.x & 31;
    const float* qr = q + (long)e_data[b * S_] * NQ1;
    float acc = 0.0f;
    for (int n = w; n < NQ1; n += 8) {
        float qv = qr[n];
        if (qv != 0.0f) acc = fmaf(qv, h0[n * DK_ + lane], acc);
    }
    atomicAdd(&g_ht[b * DK_ + lane], acc);
}

// ---------------------------------------------------------------------------
// k_seq: persistent, 296 blocks (batches 0-39: 5 blocks, 40-63: 4), 256 thr,
// 2 CTAs/SM. Per 64-row chunk each warp owns rows 8w..8w+7: computes
// z = W4h·h via tf32 mma (3-term hi/lo) AND epilogues its own accumulators
// (dims g2+8m, rows 2tg/2tg+1). No cross-warp exchange -> no per-chunk sync.
// ---------------------------------------------------------------------------
__global__ void __launch_bounds__(256, 2)
k_seq(const int* __restrict__ e_data, const float* __restrict__ q,
      const float* __restrict__ E_e,
      const float* __restrict__ W2, const float* __restrict__ b2,
      const float* __restrict__ W3, const float* __restrict__ b3,
      const float* __restrict__ W4, const float* __restrict__ b4,
      const float* __restrict__ W5, const float* __restrict__ b5,
      float* __restrict__ pred) {
    __shared__ __align__(16) float sh_h[2][2048];   // 2 x 8KB
    __shared__ __align__(16) float sh_qe[2][72];
    __shared__ __align__(16) float sh_qn[2][72];
    __shared__ __align__(8)  ull   sh_mbar[2];
    __shared__ int   sh_cnt[2];
    __shared__ float sh_x[4 * DK_];
    __shared__ float sh_LG[DK_];
    __shared__ float sh_cv[DK_];
    __shared__ float sh_gl[DK_];
    __shared__ float sh_cB[DK_];

    const int g = blockIdx.x;
    const int tid = threadIdx.x;
    const int w = tid >> 5;
    const int lane = tid & 31;
    const int g2 = lane >> 2;
    const int tg = lane & 3;

    int b, ib, nb;
    if (g < 200) { b = g / 5; ib = g - b * 5; nb = 5; }
    else { int h2 = g - 200; int bb = h2 >> 2; b = 40 + bb; ib = h2 & 3; nb = 4; }
    const int clo = (ib * NCH64) / nb;
    const int chi = ((ib + 1) * NCH64) / nb;
    const int nch = chi - clo;
    const int total_u = TSTEPS * nch;

    const unsigned mb_full = smem_u32(&sh_mbar[0]);

    if (tid == 0) {
#pragma unroll
        for (int s = 0; s < 2; s++) {
            asm volatile("mbarrier.init.shared.b64 [%0], 1;" :: "r"(mb_full + s * 8));
            sh_cnt[s] = 0;
        }
        asm volatile("fence.proxy.async.shared::cta;" ::: "memory");
    }
    __syncthreads();

#define ISSUE_U(U)                                                                      \
    {                                                                                   \
        int tu = (U) / nch;                                                             \
        int cu = (U) - tu * nch;                                                        \
        int gc = clo + cu;                                                              \
        int rs_ = gc * 64;                                                              \
        int sl_ = (U) & 1;                                                              \
        unsigned mb = mb_full + sl_ * 8;                                                \
        int etu = e_data[b * S_ + tu];                                                  \
        int enu = e_data[b * S_ + tu + 1];                                              \
        ull pe = (ull)(q + (long)etu * NQ1 + rs_);                                      \
        ull pn = (ull)(q + (long)enu * NQ1 + rs_);                                      \
        unsigned qeb = ((256u + (unsigned)(pe & 15)) + 15) & ~15u;                      \
        unsigned qnb = ((256u + (unsigned)(pn & 15)) + 15) & ~15u;                      \
        asm volatile("mbarrier.arrive.expect_tx.shared.b64 _, [%0], %1;"                \
                     :: "r"(mb), "r"(8192u + qeb + qnb) : "memory");                    \
        bulk_g2s(smem_u32(&sh_h[sl_][0]), g_h + ((size_t)b * NMC + 2 * gc) * 1024,      \
                 8192u, mb);                                                            \
        bulk_g2s(smem_u32(&sh_qe[sl_][0]), (const void*)(pe & ~15ULL), qeb, mb);        \
        bulk_g2s(smem_u32(&sh_qn[sl_][0]), (const void*)(pn & ~15ULL), qnb, mb);        \
    }

    if (tid == 0) { ISSUE_U(0) ISSUE_U(1) }

    // ---- W4h fragments (hi/lo), loaded once ----
    float ah[2][4][4], al[2][4][4];
#pragma unroll
    for (int mt = 0; mt < 2; mt++)
#pragma unroll
        for (int kt = 0; kt < 4; kt++) {
            int d0 = g2 + 16 * mt, d1 = d0 + 8;
            int k0 = 8 * kt + tg,  k1 = k0 + 4;
            float v0 = W4[d0 * 96 + k0];
            float v1 = W4[d1 * 96 + k0];
            float v2 = W4[d0 * 96 + k1];
            float v3 = W4[d1 * 96 + k1];
            ah[mt][kt][0] = tf32hi(v0); al[mt][kt][0] = v0 - ah[mt][kt][0];
            ah[mt][kt][1] = tf32hi(v1); al[mt][kt][1] = v1 - ah[mt][kt][1];
            ah[mt][kt][2] = tf32hi(v2); al[mt][kt][2] = v2 - ah[mt][kt][2];
            ah[mt][kt][3] = tf32hi(v3); al[mt][kt][3] = v3 - ah[mt][kt][3];
        }

    // Per-warp constants for its 8-row n-tile
    const int nlo = (8 * w) & 31;                  // row base within microchunk
    const int mcw = w >> 2;                        // microchunk index (0/1)
    const int xr  = (nlo + g2) ^ (8 * tg);         // B-frag swizzled row
    const int rc0 = 8 * w + 2 * tg;                // chunk-row of frag row j=0
    const int xob = 8 * (g2 & 3);
    const int xo0 = (nlo + 2 * tg) ^ xob;          // store/load col for row j0
    const int xo1 = (nlo + 2 * tg + 1) ^ xob;      // ... row j1
    int u = 0;

    for (int t = 0; t < TSTEPS; t++) {
        if (t > 0) {
            if (tid == 0) {
                int need = nb * t;
                int v;
                do {
                    asm volatile("ld.global.acquire.gpu.b32 %0, [%1];"
                                 : "=r"(v) : "l"(&g_flag[b]));
                    if (v >= need) break;
                    __nanosleep(64);
                } while (true);
            }
            __syncthreads();
        }

        const int e_t = e_data[b * S_ + t];
        const int e_n = e_data[b * S_ + t + 1];

        // ---- prologue: warps 0 (lg), 1 (gl), 2 (cB); warp 3 y-pred ----
        if (w < 3) {
            if (w == 0) {
                sh_x[lane]           = (t == 0) ? 0.0f : g_learn[((t - 1) * B_ + b) * DK_ + lane];
                sh_x[DK_ + lane]     = g_it[(t * B_ + b) * DK_ + lane];
                sh_x[2 * DK_ + lane] = g_learn[(t * B_ + b) * DK_ + lane];
                sh_x[3 * DK_ + lane] = g_ht[(t * B_ + b) * DK_ + lane];
            }
            asm volatile("bar.sync 7, 96;" ::: "memory");
            float lg = 0.0f;
            if (w == 0) {
                const float4* wk = (const float4*)(W2 + lane * 128);
                const float4* xv4 = (const float4*)sh_x;
                float a0 = b2[lane], a1 = 0.f, a2 = 0.f, a3 = 0.f;
#pragma unroll
                for (int j = 0; j < 32; j++) {
                    float4 xv = xv4[j]; float4 wa = wk[j];
                    a0 = fmaf(xv.x, wa.x, a0); a1 = fmaf(xv.y, wa.y, a1);
                    a2 = fmaf(xv.z, wa.z, a2); a3 = fmaf(xv.w, wa.w, a3);
                }
                lg = (a0 + a1) + (a2 + a3);
            } else if (w == 1) {
                const float4* wk = (const float4*)(W3 + lane * 128);
                const float4* xv4 = (const float4*)sh_x;
                float a0 = b3[lane], a1 = 0.f, a2 = 0.f, a3 = 0.f;
#pragma unroll
                for (int j = 0; j < 32; j++) {
                    float4 xv = xv4[j]; float4 wa = wk[j];
                    a0 = fmaf(xv.x, wa.x, a0); a1 = fmaf(xv.y, wa.y, a1);
                    a2 = fmaf(xv.z, wa.z, a2); a3 = fmaf(xv.w, wa.w, a3);
                }
                float gl = (a0 + a1) + (a2 + a3);
                sh_gl[lane] = 1.0f / (1.0f + expf(-gl));
            } else {
                const float* wk = W4 + lane * (3 * DK_) + 2 * DK_;
                float a0 = b4[lane], a1 = 0.f;
#pragma unroll
                for (int j = 0; j < DK_; j += 2) {
                    a0 = fmaf(sh_x[DK_ + j],     wk[j],     a0);
                    a1 = fmaf(sh_x[DK_ + j + 1], wk[j + 1], a1);
                }
                sh_cB[lane] = a0 + a1;
            }
            asm volatile("bar.sync 7, 96;" ::: "memory");
            if (w == 0) {
                lg = tanhf(lg);
                sh_LG[lane] = sh_gl[lane] * (lg + 1.0f) * 0.5f;
                __syncwarp();
                const float* w4l = W4 + lane * (3 * DK_) + DK_;
                float c0 = sh_cB[lane], c1 = 0.f;
#pragma unroll
                for (int j = 0; j < DK_; j += 2) {
                    c0 = fmaf(sh_LG[j],     w4l[j],     c0);
                    c1 = fmaf(sh_LG[j + 1], w4l[j + 1], c1);
                }
                sh_cv[lane] = c0 + c1;
            }
        } else if (w == 3 && ib == 0 && t > 0) {
            const float* ee = E_e + e_t * DK_;
            const float* ht = g_ht + (t * B_ + b) * DK_;
            const float* w5k = W5 + lane * (2 * DK_);
            float z = b5[lane];
#pragma unroll
            for (int j = 0; j < DK_; j++) {
                z = fmaf(ee[j], w5k[j], z);
                z = fmaf(ht[j], w5k[DK_ + j], z);
            }
            float s = 1.0f / (1.0f + expf(-z));
#pragma unroll
            for (int off = 16; off; off >>= 1)
                s += __shfl_xor_sync(0xffffffffu, s, off);
            if (lane == 0) pred[b * S_ + t] = s * (1.0f / DK_);
        }
        __syncthreads();

        // per-step per-thread constants for its 4 dims
        float cvd[4], LGd[4];
#pragma unroll
        for (int m = 0; m < 4; m++) {
            cvd[m] = sh_cv[g2 + 8 * m];
            LGd[m] = sh_LG[g2 + 8 * m];
        }
        float* htn = g_ht + ((t + 1) * B_ + b) * DK_;

        for (int c = 0; c < nch; c++, u++) {
            const int slot = u & 1;
            const unsigned phase = (u >> 1) & 1;
            mbar_wait(mb_full + slot * 8, phase);

            const int gc = clo + c;
            const int rs = gc * 64;
            float* tloc = sh_h[slot] + (mcw << 10);

            // ---- B frags + 3-term tf32 mma (layouts validated in R13) ----
            float bh[4][2], bl[4][2];
#pragma unroll
            for (int kt = 0; kt < 4; kt++) {
                int k0 = 8 * kt + tg;
                float v0 = tloc[k0 * 32 + xr];
                float v1 = tloc[(k0 + 4) * 32 + xr];
                bh[kt][0] = tf32hi(v0); bl[kt][0] = v0 - bh[kt][0];
                bh[kt][1] = tf32hi(v1); bl[kt][1] = v1 - bh[kt][1];
            }
            float C0[4] = {0.f, 0.f, 0.f, 0.f};
            float C1[4] = {0.f, 0.f, 0.f, 0.f};
#pragma unroll
            for (int kt = 0; kt < 4; kt++) {
                mma8(C0, ah[0][kt], bh[kt]);
                mma8(C1, ah[1][kt], bh[kt]);
            }
#pragma unroll
            for (int kt = 0; kt < 4; kt++) {
                mma8(C0, ah[0][kt], bl[kt]);
                mma8(C1, ah[1][kt], bl[kt]);
            }
#pragma unroll
            for (int kt = 0; kt < 4; kt++) {
                mma8(C0, al[0][kt], bh[kt]);
                mma8(C1, al[1][kt], bh[kt]);
            }

            // ---- in-warp epilogue: this thread's 2 rows x 4 dims ----
            const int qoe = (int)(((ull)(q + (long)e_t * NQ1 + rs) >> 2) & 3);
            const int qon = (int)(((ull)(q + (long)e_n * NQ1 + rs) >> 2) & 3);
            const bool v0ok = (rs + rc0) < NQ1;
            const bool v1ok = (rs + rc0 + 1) < NQ1;
            const float qe0 = v0ok ? sh_qe[slot][qoe + rc0]     : 0.0f;
            const float qe1 = v1ok ? sh_qe[slot][qoe + rc0 + 1] : 0.0f;
            const float qn0 = v0ok ? sh_qn[slot][qon + rc0]     : 0.0f;
            const float qn1 = v1ok ? sh_qn[slot][qon + rc0 + 1] : 0.0f;
            float* gob = g_h + ((size_t)b * NMC + 2 * gc + mcw) * 1024;

#define EPI(Z0, Z1, M)                                                         \
    {                                                                          \
        const int dim = g2 + 8 * (M);                                          \
        float hk0 = tloc[dim * 32 + xo0];                                      \
        float hk1 = tloc[dim * 32 + xo1];                                      \
        float gm0 = __fdividef(1.0f, 1.0f + __expf(-((Z0) + cvd[M])));         \
        float gm1 = __fdividef(1.0f, 1.0f + __expf(-((Z1) + cvd[M])));         \
        float hn0 = fmaf(gm0, hk0, qe0 * LGd[M]);                              \
        float hn1 = fmaf(gm1, hk1, qe1 * LGd[M]);                              \
        gob[dim * 32 + xo0] = hn0;                                             \
        gob[dim * 32 + xo1] = hn1;                                             \
        if (qn0 != 0.0f) atomicAdd(htn + dim, qn0 * hn0);                      \
        if (qn1 != 0.0f) atomicAdd(htn + dim, qn1 * hn1);                      \
    }
            EPI(C0[0], C0[1], 0)
            EPI(C0[2], C0[3], 1)
            EPI(C1[0], C1[1], 2)
            EPI(C1[2], C1[3], 3)
#undef EPI

            // last-finisher election issues the refill for u+2
            if (lane == 0) {
                int old = atomicAdd(&sh_cnt[slot], 1);
                if ((old & 7) == 7) {
                    __threadfence();
                    const int un = u + 2;
                    if (un < total_u) ISSUE_U(un)
                }
            }
        }

        __threadfence();
        __syncthreads();
        if (tid == 0 && t < TSTEPS - 1) atomicAdd(&g_flag[b], 1);
    }
#undef ISSUE_U
}

// ---------------------------------------------------------------------------
__global__ void k_final(const int* __restrict__ e_data, const float* __restrict__ E_e,
                        const float* __restrict__ W5, const float* __restrict__ b5,
                        float* __restrict__ pred) {
    int b = blockIdx.x;
    int k = threadIdx.x;
    int tlast = S_ - 1;
    int en = e_data[b * S_ + tlast];
    const float* ee = E_e + en * DK_;
    const float* ht = g_ht + (tlast * B_ + b) * DK_;
    const float* w5k = W5 + k * (2 * DK_);
    float z = b5[k];
#pragma unroll
    for (int j = 0; j < DK_; j++) {
        z = fmaf(ee[j], w5k[j], z);
        z = fmaf(ht[j], w5k[DK_ + j], z);
    }
    float s = 1.0f / (1.0f + expf(-z));
#pragma unroll
    for (int off = 16; off; off >>= 1)
        s += __shfl_xor_sync(0xffffffffu, s, off);
    if (k == 0) pred[b * S_ + tlast] = s * (1.0f / DK_);
}

// ---------------------------------------------------------------------------
extern "C" void kernel_launch(void* const* d_in, const int* in_sizes, int n_in,
                              void* d_out, int out_size) {
    const int*   e_data  = (const int*)d_in[0];
    const int*   at_data = (const int*)d_in[1];
    const int*   it_data = (const int*)d_in[2];
    const float* a_data  = (const float*)d_in[3];
    const float* q       = (const float*)d_in[4];
    const float* E_e     = (const float*)d_in[5];
    const float* E_at    = (const float*)d_in[6];
    const float* E_it    = (const float*)d_in[7];
    const float* W1      = (const float*)d_in[8];
    const float* b1      = (const float*)d_in[9];
    const float* W2      = (const float*)d_in[10];
    const float* b2      = (const float*)d_in[11];
    const float* W3      = (const float*)d_in[12];
    const float* b3      = (const float*)d_in[13];
    const float* W4      = (const float*)d_in[14];
    const float* b4      = (const float*)d_in[15];
    const float* W5      = (const float*)d_in[16];
    const float* b5      = (const float*)d_in[17];
    const float* h0      = (const float*)d_in[18];
    float* pred = (float*)d_out;

    k_init<<<2048, 256>>>(h0, pred);
    k_embed<<<(S_ * B_ * DK_ + 255) / 256, 256>>>(e_data, at_data, it_data, a_data,
                                                  E_e, E_at, E_it, W1, b1);
    k_ht0<<<B_, 256>>>(e_data, q, h0);

    k_seq<<<NBLK, 256>>>(e_data, q, E_e, W2, b2, W3, b3, W4, b4, W5, b5, pred);

    k_final<<<B_, 32>>>(e_data, E_e, W5, b5, pred);
}